// round 10
// baseline (speedup 1.0000x reference)
#include <cuda_runtime.h>
#include <cuda_bf16.h>
#include <math.h>
#include <stdint.h>

// Problem constants
#define B  64
#define L  2048
#define H  1024
#define V  32000
#define P  128
#define H2 2048          // 2*H
#define KO 1152          // H + P

#define CHUNKS 64        // L-splits for attention
#define LC (L / CHUNKS)  // 32
#define PS (H + 4)       // partial stride (16B aligned)

typedef unsigned long long U64;

union U64F2 { U64 u; float2 f; };

__device__ __forceinline__ U64 fma2(U64 a, U64 b, U64 c) {
    U64 d;
    asm("fma.rn.f32x2 %0, %1, %2, %3;" : "=l"(d) : "l"(a), "l"(b), "l"(c));
    return d;
}
__device__ __forceinline__ U64 mul2(U64 a, U64 b) {
    U64 d;
    asm("mul.rn.f32x2 %0, %1, %2;" : "=l"(d) : "l"(a), "l"(b));
    return d;
}
__device__ __forceinline__ float hsum2(U64 a) {
    U64F2 t; t.u = a; return t.f.x + t.f.y;
}
__device__ __forceinline__ U64 dup2(float x) {
    U64F2 t; t.f.x = x; t.f.y = x; return t.u;
}
__device__ __forceinline__ U64 pack2(float x, float y) {
    U64F2 t; t.f.x = x; t.f.y = y; return t.u;
}
// pack two floats to half2: lo = x (even k), hi = y
__device__ __forceinline__ uint32_t f2h2(float x, float y) {
    uint32_t r;
    asm("cvt.rn.f16x2.f32 %0, %1, %2;" : "=r"(r) : "f"(y), "f"(x));
    return r;
}
__device__ __forceinline__ uint32_t smem_u32(const void* p) {
    uint32_t a;
    asm("{ .reg .u64 t; cvta.to.shared.u64 t, %1; cvt.u32.u64 %0, t; }"
        : "=r"(a) : "l"(p));
    return a;
}

#define CP_ASYNC16(dst, src) \
    asm volatile("cp.async.cg.shared.global [%0], [%1], 16;" \
                 :: "r"(dst), "l"(src) : "memory")
#define CP_COMMIT  asm volatile("cp.async.commit_group;" ::: "memory")
#define CP_WAIT_1  asm volatile("cp.async.wait_group 1;" ::: "memory")
#define CP_WAIT_0  asm volatile("cp.async.wait_group 0;" ::: "memory")

// Scratch (device globals — no allocation allowed)
__device__ float g_hnew[B * H];
__device__ float g_cat[B * H2];                 // [h_new | context]
__device__ float g_catp[B * KO];                // [concat_out | prior]
__device__ float g_energy[B * L];
__device__ float g_part[B * CHUNKS * PS];       // ctx partial + (m, s)
__device__ float g_pih[4 * B * 3 * H];          // GRU ih partials (ksplit=4)
__device__ float g_phh[4 * B * 3 * H];          // GRU hh partials
__device__ float g_pcc[16 * B * H];             // concat partials (ksplit=16)

// ---------------------------------------------------------------------------
// SIMT GEMM (GRU + concat): C[b,n] = sum_k A[b,k]*W[n,k]
// Optional row indirection for A0 (embedding gather folded in).
// ---------------------------------------------------------------------------
#define GKT 32

__global__ void __launch_bounds__(256)
gemm_kernel(const float* __restrict__ A0, const float* __restrict__ A1,
            const float* __restrict__ W0, const float* __restrict__ W1,
            float* __restrict__ C0, float* __restrict__ C1,
            const float* __restrict__ bias,
            int N, int K, int ksplit, int ldc,
            const int* __restrict__ gidx)     // if non-null: A0 rows = A0 + gidx[r]*K
{
    __shared__ U64 As2[16][66];
    __shared__ U64 Ws2[16][130];

    const float* A = blockIdx.z ? A1 : A0;
    const float* W = blockIdx.z ? W1 : W0;
    float*       C = blockIdx.z ? C1 : C0;
    bool use_g = (gidx != nullptr) && (blockIdx.z == 0);

    int vbase = blockIdx.x * 128;
    int kc    = K / ksplit;
    int k0    = blockIdx.y * kc;
    int tiles = kc / GKT;

    int tid = threadIdx.x;
    int vg  = tid >> 4;
    int bg  = tid & 15;
    int r8  = tid >> 3;
    int k4  = tid & 7;

    // A row base pointers for the two rows this thread loads
    const float* arow[2];
    #pragma unroll
    for (int i = 0; i < 2; i++) {
        int r = r8 + i * 32;
        size_t ro = use_g ? (size_t)__ldg(&gidx[r]) : (size_t)r;
        arow[i] = A + ro * K;
    }

    U64 acc[8][4];
    #pragma unroll
    for (int v = 0; v < 8; v++)
        #pragma unroll
        for (int j = 0; j < 4; j++) acc[v][j] = 0ull;

    float4 pa[2], pw[4];
    {
        int kt = k0 + k4 * 4;
        #pragma unroll
        for (int i = 0; i < 2; i++)
            pa[i] = *(const float4*)(arow[i] + kt);
        #pragma unroll
        for (int i = 0; i < 4; i++)
            pw[i] = *(const float4*)(W + (size_t)(vbase + r8 + i * 32) * K + kt);
    }

    for (int t = 0; t < tiles; t++) {
        __syncthreads();
        #pragma unroll
        for (int i = 0; i < 2; i++) {
            int b = r8 + i * 32;
            As2[2 * k4][b]     = pack2(pa[i].x, pa[i].y);
            As2[2 * k4 + 1][b] = pack2(pa[i].z, pa[i].w);
        }
        #pragma unroll
        for (int i = 0; i < 4; i++) {
            int n = r8 + i * 32;
            Ws2[2 * k4][n]     = pack2(pw[i].x, pw[i].y);
            Ws2[2 * k4 + 1][n] = pack2(pw[i].z, pw[i].w);
        }
        __syncthreads();

        if (t + 1 < tiles) {
            int kt = k0 + (t + 1) * GKT + k4 * 4;
            #pragma unroll
            for (int i = 0; i < 2; i++)
                pa[i] = *(const float4*)(arow[i] + kt);
            #pragma unroll
            for (int i = 0; i < 4; i++)
                pw[i] = *(const float4*)(W + (size_t)(vbase + r8 + i * 32) * K + kt);
        }

        #pragma unroll
        for (int kp = 0; kp < 16; kp++) {
            ulonglong2 a01 = *(const ulonglong2*)&As2[kp][bg * 4];
            ulonglong2 a23 = *(const ulonglong2*)&As2[kp][bg * 4 + 2];
            ulonglong2 w01 = *(const ulonglong2*)&Ws2[kp][vg * 8];
            ulonglong2 w23 = *(const ulonglong2*)&Ws2[kp][vg * 8 + 2];
            ulonglong2 w45 = *(const ulonglong2*)&Ws2[kp][vg * 8 + 4];
            ulonglong2 w67 = *(const ulonglong2*)&Ws2[kp][vg * 8 + 6];
            U64 a[4] = {a01.x, a01.y, a23.x, a23.y};
            U64 w[8] = {w01.x, w01.y, w23.x, w23.y, w45.x, w45.y, w67.x, w67.y};
            #pragma unroll
            for (int v = 0; v < 8; v++) {
                acc[v][0] = fma2(a[0], w[v], acc[v][0]);
                acc[v][1] = fma2(a[1], w[v], acc[v][1]);
                acc[v][2] = fma2(a[2], w[v], acc[v][2]);
                acc[v][3] = fma2(a[3], w[v], acc[v][3]);
            }
        }
    }

    float bv[8];
    #pragma unroll
    for (int v = 0; v < 8; v++)
        bv[v] = bias ? bias[vbase + vg * 8 + v] : 0.0f;

    float* Cb = bias ? C : (C + (size_t)blockIdx.y * 64 * ldc);
    #pragma unroll
    for (int j = 0; j < 4; j++) {
        int b = bg * 4 + j;
        float4 o0, o1;
        o0.x = hsum2(acc[0][j]) + bv[0];
        o0.y = hsum2(acc[1][j]) + bv[1];
        o0.z = hsum2(acc[2][j]) + bv[2];
        o0.w = hsum2(acc[3][j]) + bv[3];
        o1.x = hsum2(acc[4][j]) + bv[4];
        o1.y = hsum2(acc[5][j]) + bv[5];
        o1.z = hsum2(acc[6][j]) + bv[6];
        o1.w = hsum2(acc[7][j]) + bv[7];
        float* cp = Cb + (size_t)b * ldc + vbase + vg * 8;
        *(float4*)cp       = o0;
        *(float4*)(cp + 4) = o1;
    }
}

// ---------------------------------------------------------------------------
// GRU gates
// ---------------------------------------------------------------------------
__global__ void gru_gates_kernel(const float* __restrict__ lh,
                                 const float* __restrict__ bih,
                                 const float* __restrict__ bhh,
                                 float* __restrict__ out_h)
{
    int idx = blockIdx.x * 256 + threadIdx.x;
    int b = idx >> 10;
    int c = idx & 1023;

    float gir = 0.f, giz = 0.f, gin = 0.f, ghr = 0.f, ghz = 0.f, ghn = 0.f;
    #pragma unroll
    for (int s = 0; s < 4; s++) {
        size_t base = ((size_t)(s * 64 + b)) * (3 * H) + c;
        gir += g_pih[base];
        giz += g_pih[base + H];
        gin += g_pih[base + 2 * H];
        ghr += g_phh[base];
        ghz += g_phh[base + H];
        ghn += g_phh[base + 2 * H];
    }
    gir += bih[c]; giz += bih[c + H]; gin += bih[c + 2 * H];
    ghr += bhh[c]; ghz += bhh[c + H]; ghn += bhh[c + 2 * H];

    float r = 1.0f / (1.0f + expf(-(gir + ghr)));
    float z = 1.0f / (1.0f + expf(-(giz + ghz)));
    float n = tanhf(gin + r * ghn);
    float hp = lh[(size_t)b * H + c];
    float hn = (1.0f - z) * n + z * hp;

    g_hnew[(size_t)b * H + c] = hn;
    g_cat[(size_t)b * H2 + c] = hn;
    if (out_h) out_h[(size_t)b * H + c] = hn;
}

// ---------------------------------------------------------------------------
// concat reduce
// ---------------------------------------------------------------------------
__global__ void creduce_kernel(const float* __restrict__ bc)
{
    int idx = blockIdx.x * 256 + threadIdx.x;
    int b = idx >> 10;
    int c = idx & 1023;
    float s = 0.f;
    #pragma unroll
    for (int k = 0; k < 16; k++)
        s += g_pcc[((size_t)(k * 64 + b)) * H + c];
    g_catp[(size_t)b * KO + c] = tanhf(s + bc[c]);
}

// ---------------------------------------------------------------------------
// Attention pass 1: cp.async 2-stage pipelined flash attention (R8 version).
// ---------------------------------------------------------------------------
extern __shared__ float attn_smem[];   // 4 warps * 2 stages * 2 rows * H floats

__global__ void __launch_bounds__(128)
attn1_kernel(const float* __restrict__ enc)
{
    int warp = threadIdx.x >> 5;
    int lane = threadIdx.x & 31;
    int gw   = blockIdx.x * 4 + warp;
    int b    = gw >> 6;
    int ch   = gw & 63;
    int l0   = ch * LC;

    uint32_t wbase = smem_u32(attn_smem) + warp * 16384u;
    float*   wptr  = attn_smem + warp * 4096;

    U64 q[16];
    {
        const float* qp = g_hnew + (size_t)b * H;
        #pragma unroll
        for (int j = 0; j < 8; j++) {
            ulonglong2 v = *(const ulonglong2*)(qp + j * 128 + lane * 4);
            q[2 * j] = v.x; q[2 * j + 1] = v.y;
        }
    }

    U64 cacc[16];
    #pragma unroll
    for (int i = 0; i < 16; i++) cacc[i] = 0ull;
    float m = -1e30f, s = 0.0f;

    {
        const float* eg0 = enc + ((size_t)l0 * B + b) * H + lane * 4;
        uint32_t d0 = wbase + lane * 16u;
        #pragma unroll
        for (int j = 0; j < 8; j++) {
            CP_ASYNC16(d0 + j * 512u,          eg0 + j * 128);
            CP_ASYNC16(d0 + 4096u + j * 512u,  eg0 + (size_t)B * H + j * 128);
        }
        CP_COMMIT;
    }

    #pragma unroll 1
    for (int i = 0; i < LC / 2; i++) {
        int stage = i & 1;

        if (i + 1 < LC / 2) {
            const float* eg0 = enc + ((size_t)(l0 + 2 * (i + 1)) * B + b) * H + lane * 4;
            uint32_t d0 = wbase + (uint32_t)((stage ^ 1) * 8192) + lane * 16u;
            #pragma unroll
            for (int j = 0; j < 8; j++) {
                CP_ASYNC16(d0 + j * 512u,          eg0 + j * 128);
                CP_ASYNC16(d0 + 4096u + j * 512u,  eg0 + (size_t)B * H + j * 128);
            }
            CP_COMMIT;
            CP_WAIT_1;
        } else {
            CP_WAIT_0;
        }

        const float* sb = wptr + stage * 2048 + lane * 4;
        U64 ev0[16], ev1[16];
        #pragma unroll
        for (int j = 0; j < 8; j++) {
            ulonglong2 v0 = *(const ulonglong2*)(sb + j * 128);
            ulonglong2 v1 = *(const ulonglong2*)(sb + 1024 + j * 128);
            ev0[2 * j] = v0.x; ev0[2 * j + 1] = v0.y;
            ev1[2 * j] = v1.x; ev1[2 * j + 1] = v1.y;
        }

        U64 ea0 = 0ull, ea1 = 0ull;
        #pragma unroll
        for (int k = 0; k < 16; k++) {
            ea0 = fma2(ev0[k], q[k], ea0);
            ea1 = fma2(ev1[k], q[k], ea1);
        }
        float e0 = hsum2(ea0);
        float e1 = hsum2(ea1);
        #pragma unroll
        for (int off = 16; off > 0; off >>= 1) {
            e0 += __shfl_xor_sync(0xffffffffu, e0, off);
            e1 += __shfl_xor_sync(0xffffffffu, e1, off);
        }

        if (lane == 0) {
            g_energy[(size_t)b * L + l0 + 2 * i]     = e0;
            g_energy[(size_t)b * L + l0 + 2 * i + 1] = e1;
        }

        float mn = fmaxf(m, fmaxf(e0, e1));
        float sc = expf(m - mn);
        float p0 = expf(e0 - mn);
        float p1 = expf(e1 - mn);
        s = s * sc + p0 + p1;
        m = mn;
        U64 sc2 = dup2(sc), pp0 = dup2(p0), pp1 = dup2(p1);
        #pragma unroll
        for (int k = 0; k < 16; k++) {
            U64 t = mul2(cacc[k], sc2);
            t = fma2(ev0[k], pp0, t);
            cacc[k] = fma2(ev1[k], pp1, t);
        }
    }

    float* pb = g_part + (size_t)(b * CHUNKS + ch) * PS;
    #pragma unroll
    for (int j = 0; j < 8; j++) {
        ulonglong2 w;
        w.x = cacc[2 * j]; w.y = cacc[2 * j + 1];
        *(ulonglong2*)(pb + j * 128 + lane * 4) = w;
    }
    if (lane == 0) { pb[H] = m; pb[H + 1] = s; }
}

// ---------------------------------------------------------------------------
// Combine partials
// ---------------------------------------------------------------------------
__global__ void combine_kernel(const float* __restrict__ prior,
                               float* __restrict__ out, int write_attn)
{
    int b = blockIdx.x;
    int t = threadIdx.x;

    __shared__ float shm[CHUNKS], shs[CHUNKS], shw[CHUNKS];
    __shared__ float shM, shS;

    if (t < CHUNKS) {
        shm[t] = g_part[(size_t)(b * CHUNKS + t) * PS + H];
        shs[t] = g_part[(size_t)(b * CHUNKS + t) * PS + H + 1];
    }
    __syncthreads();
    if (t < 32) {
        float M = fmaxf(shm[t], shm[t + 32]);
        #pragma unroll
        for (int off = 16; off > 0; off >>= 1)
            M = fmaxf(M, __shfl_xor_sync(0xffffffffu, M, off));
        if (t == 0) shM = M;
    }
    __syncthreads();
    float M = shM;
    if (t < CHUNKS) shw[t] = expf(shm[t] - M);
    __syncthreads();
    if (t < 32) {
        float S = shs[t] * shw[t] + shs[t + 32] * shw[t + 32];
        #pragma unroll
        for (int off = 16; off > 0; off >>= 1)
            S += __shfl_xor_sync(0xffffffffu, S, off);
        if (t == 0) shS = S;
    }
    __syncthreads();
    float invS = 1.0f / shS;

    {
        int h = t * 4;
        float4 acc = make_float4(0.f, 0.f, 0.f, 0.f);
        #pragma unroll 4
        for (int i = 0; i < CHUNKS; i++) {
            float4 v = *(const float4*)(g_part + (size_t)(b * CHUNKS + i) * PS + h);
            float w = shw[i];
            acc.x += w * v.x; acc.y += w * v.y;
            acc.z += w * v.z; acc.w += w * v.w;
        }
        float4 o = make_float4(acc.x * invS, acc.y * invS, acc.z * invS, acc.w * invS);
        *(float4*)(g_cat + (size_t)b * H2 + H + h) = o;
    }

    if (write_attn) {
        size_t base = (size_t)B * V + (size_t)B * H + (size_t)b * L;
        for (int l = t; l < L; l += blockDim.x)
            out[base + l] = expf(g_energy[(size_t)b * L + l] - M) * invS;
    }

    for (int p = t; p < P; p += blockDim.x)
        g_catp[(size_t)b * KO + H + p] = prior[(size_t)b * P + p];
}

// ---------------------------------------------------------------------------
// Output GEMM via mma.sync fp16 (m16n8k16). Block = 128v x 64b, 8 warps (2x4),
// warp tile 64m x 16n. K-tiles of 64, double-buffered dyn smem (54 KB),
// one sync per tile; per iter: sync -> STS(t+1) -> LDG(t+2) -> MMA(t).
// Smem as half2 with row stride 36 uint32 (32 data + 4 pad) -> conflict-free.
// ---------------------------------------------------------------------------
#define OKT 64
#define OTILES (KO / OKT)   // 18
#define HSTRIDE 36          // uint32 (half2) per row
#define A_SMW (128 * HSTRIDE)
#define B_SMW (64 * HSTRIDE)
#define OG_SMEM_BYTES ((2 * A_SMW + 2 * B_SMW) * 4)   // 55296 B

__device__ __forceinline__ void mma_f16(float* d, uint32_t a0, uint32_t a1,
                                        uint32_t a2, uint32_t a3,
                                        uint32_t b0, uint32_t b1)
{
    asm volatile(
        "mma.sync.aligned.m16n8k16.row.col.f32.f16.f16.f32 "
        "{%0,%1,%2,%3}, {%4,%5,%6,%7}, {%8,%9}, {%0,%1,%2,%3};"
        : "+f"(d[0]), "+f"(d[1]), "+f"(d[2]), "+f"(d[3])
        : "r"(a0), "r"(a1), "r"(a2), "r"(a3), "r"(b0), "r"(b1));
}

extern __shared__ uint32_t og_smem[];

__global__ void __launch_bounds__(256)
out_gemm_tc_kernel(const float* __restrict__ Wout,
                   const float* __restrict__ bout,
                   float* __restrict__ outp)
{
    uint32_t* A_h[2] = {og_smem, og_smem + A_SMW};
    uint32_t* B_h[2] = {og_smem + 2 * A_SMW, og_smem + 2 * A_SMW + B_SMW};

    int tid   = threadIdx.x;
    int wid   = tid >> 5;
    int lane  = tid & 31;
    int gid   = lane >> 2;
    int tig   = lane & 3;
    int vbase = blockIdx.x * 128;

    int warp_m = wid & 1;
    int warp_n = wid >> 1;
    int mbase  = warp_m * 64;
    int nbase  = warp_n * 16;

    // load indexing: A 8 float4/thread, B 4 float4/thread
    int a_row  = tid >> 1;            // 0..127
    int a_half = tid & 1;             // 0..1 : col4 = half*8 + j
    int b_row  = tid >> 2;            // 0..63
    int b_q    = tid & 3;             // 0..3 : col4 = q*4 + j

    float acc[4][2][4];
    #pragma unroll
    for (int mt = 0; mt < 4; mt++)
        #pragma unroll
        for (int nt = 0; nt < 2; nt++)
            #pragma unroll
            for (int i = 0; i < 4; i++) acc[mt][nt][i] = 0.0f;

    float4 pa[8], pb[4];

    const float* Arow = Wout + (size_t)(vbase + a_row) * KO;
    const float* Brow = g_catp + (size_t)b_row * KO;

    // helper offsets in floats
    // prologue: tile0 -> regs -> buf0 ; tile1 -> regs
    #pragma unroll
    for (int j = 0; j < 8; j++)
        pa[j] = *(const float4*)(Arow + (a_half * 8 + j) * 4);
    #pragma unroll
    for (int j = 0; j < 4; j++)
        pb[j] = *(const float4*)(Brow + (b_q * 4 + j) * 4);

    #pragma unroll
    for (int j = 0; j < 8; j++)
        *(uint2*)&A_h[0][a_row * HSTRIDE + (a_half * 8 + j) * 2] =
            make_uint2(f2h2(pa[j].x, pa[j].y), f2h2(pa[j].z, pa[j].w));
    #pragma unroll
    for (int j = 0; j < 4; j++)
        *(uint2*)&B_h[0][b_row * HSTRIDE + (b_q * 4 + j) * 2] =
            make_uint2(f2h2(pb[j].x, pb[j].y), f2h2(pb[j].z, pb[j].w));

    if (OTILES > 1) {
        #pragma unroll
        for (int j = 0; j < 8; j++)
            pa[j] = *(const float4*)(Arow + OKT + (a_half * 8 + j) * 4);
        #pragma unroll
        for (int j = 0; j < 4; j++)
            pb[j] = *(const float4*)(Brow + OKT + (b_q * 4 + j) * 4);
    }

    #pragma unroll 1
    for (int t = 0; t < OTILES; t++) {
        __syncthreads();   // buf[t&1] ready; buf[(t+1)&1] free for writing
        int buf = t & 1;

        // STS tile t+1 into the other buffer (regs hold tile t+1)
        if (t + 1 < OTILES) {
            int nbuf = buf ^ 1;
            #pragma unroll
            for (int j = 0; j < 8; j++)
                *(uint2*)&A_h[nbuf][a_row * HSTRIDE + (a_half * 8 + j) * 2] =
                    make_uint2(f2h2(pa[j].x, pa[j].y), f2h2(pa[j].z, pa[j].w));
            #pragma unroll
            for (int j = 0; j < 4; j++)
                *(uint2*)&B_h[nbuf][b_row * HSTRIDE + (b_q * 4 + j) * 2] =
                    make_uint2(f2h2(pb[j].x, pb[j].y), f2h2(pb[j].z, pb[j].w));
        }
        // LDG tile t+2 into regs (in flight across this tile's MMA phase)
        if (t + 2 < OTILES) {
            int kt = (t + 2) * OKT;
            #pragma unroll
            for (int j = 0; j < 8; j++)
                pa[j] = *(const float4*)(Arow + kt + (a_half * 8 + j) * 4);
            #pragma unroll
            for (int j = 0; j < 4; j++)
                pb[j] = *(const float4*)(Brow + kt + (b_q * 4 + j) * 4);
        }

        // MMA over buf: 4 k16 chunks per 64-k tile
        #pragma unroll
        for (int kb = 0; kb < 4; kb++) {
            int k2 = kb * 8 + tig;

            uint32_t bf0[2], bf1[2];
            #pragma unroll
            for (int nt = 0; nt < 2; nt++) {
                int n0 = nbase + nt * 8 + gid;
                bf0[nt] = B_h[buf][n0 * HSTRIDE + k2];
                bf1[nt] = B_h[buf][n0 * HSTRIDE + k2 + 4];
            }
            #pragma unroll
            for (int mt = 0; mt < 4; mt++) {
                int r0 = mbase + mt * 16 + gid;
                uint32_t a0 = A_h[buf][r0 * HSTRIDE + k2];
                uint32_t a1 = A_h[buf][(r0 + 8) * HSTRIDE + k2];
                uint32_t a2 = A_h[buf][r0 * HSTRIDE + k2 + 4];
                uint32_t a3 = A_h[buf][(r0 + 8) * HSTRIDE + k2 + 4];
                mma_f16(acc[mt][0], a0, a1, a2, a3, bf0[0], bf1[0]);
                mma_f16(acc[mt][1], a0, a1, a2, a3, bf0[1], bf1[1]);
            }
        }
    }

    // epilogue: D[v, b] -> outp[b*V + v] + bias[v]
    #pragma unroll
    for (int mt = 0; mt < 4; mt++) {
        int v0 = vbase + mbase + mt * 16 + gid;
        float bias0 = bout[v0];
        float bias1 = bout[v0 + 8];
        #pragma unroll
        for (int nt = 0; nt < 2; nt++) {
            int bcol = nbase + nt * 8 + 2 * tig;
            outp[(size_t)bcol * V + v0]           = acc[mt][nt][0] + bias0;
            outp[(size_t)(bcol + 1) * V + v0]     = acc[mt][nt][1] + bias0;
            outp[(size_t)bcol * V + v0 + 8]       = acc[mt][nt][2] + bias1;
            outp[(size_t)(bcol + 1) * V + v0 + 8] = acc[mt][nt][3] + bias1;
        }
    }
}

// ---------------------------------------------------------------------------
extern "C" void kernel_launch(void* const* d_in, const int* in_sizes, int n_in,
                              void* d_out, int out_size)
{
    const int*   seq   = (const int*)d_in[0];   // int32 (JAX x64 disabled)
    const float* lh    = (const float*)d_in[1];
    const float* enc   = (const float*)d_in[2];
    const float* prior = (const float*)d_in[3];
    const float* emb   = (const float*)d_in[4];
    const float* Wih   = (const float*)d_in[5];
    const float* Whh   = (const float*)d_in[6];
    const float* bih   = (const float*)d_in[7];
    const float* bhh   = (const float*)d_in[8];
    const float* Wc    = (const float*)d_in[9];
    const float* bc    = (const float*)d_in[10];
    const float* Wout  = (const float*)d_in[11];
    const float* bout  = (const float*)d_in[12];

    float* out = (float*)d_out;
    long long need_h    = (long long)B * V + (long long)B * H;
    long long need_attn = need_h + (long long)B * L;
    float* out_h = ((long long)out_size >= need_h) ? out + (size_t)B * V : nullptr;
    int write_attn = ((long long)out_size >= need_attn) ? 1 : 0;

    float* pih; cudaGetSymbolAddress((void**)&pih, g_pih);
    float* phh; cudaGetSymbolAddress((void**)&phh, g_phh);
    float* pcc; cudaGetSymbolAddress((void**)&pcc, g_pcc);
    float* gcat; cudaGetSymbolAddress((void**)&gcat, g_cat);

    cudaFuncSetAttribute(attn1_kernel,
                         cudaFuncAttributeMaxDynamicSharedMemorySize, 65536);
    cudaFuncSetAttribute(out_gemm_tc_kernel,
                         cudaFuncAttributeMaxDynamicSharedMemorySize, OG_SMEM_BYTES);

    // 1. GRU GEMMs: gi = emb[seq]@Wih^T (gather folded in), gh = h@Whh^T
    gemm_kernel<<<dim3(3 * H / 128, 4, 2), 256>>>(
        emb, lh, Wih, Whh, pih, phh, nullptr, 3 * H, H, 4, 3 * H, seq);

    // 2. gates -> h_new
    gru_gates_kernel<<<B * H / 256, 256>>>(lh, bih, bhh, out_h);

    // 3. flash attention over encoder_outputs (read once, 2-stage cp.async)
    attn1_kernel<<<B * CHUNKS / 4, 128, 65536>>>(enc);

    // 4. combine -> context, attn weights, prior copy
    combine_kernel<<<B, 256>>>(prior, out, write_attn);

    // 5. concat GEMM (N=1024, K=2048, ksplit=16) + reduce/tanh
    gemm_kernel<<<dim3(H / 128, 16, 1), 256>>>(
        gcat, gcat, Wc, Wc, pcc, pcc, nullptr, H, H2, 16, H, nullptr);
    creduce_kernel<<<B * H / 256, 256>>>(bc);

    // 6. output GEMM (N=32000, K=1152) via mma.sync fp16, 64-K tiles
    out_gemm_tc_kernel<<<V / 128, 256, OG_SMEM_BYTES>>>(Wout, bout, out);
}

// round 11
// speedup vs baseline: 1.1924x; 1.1924x over previous
#include <cuda_runtime.h>
#include <cuda_bf16.h>
#include <math.h>
#include <stdint.h>

// Problem constants
#define B  64
#define L  2048
#define H  1024
#define V  32000
#define P  128
#define H2 2048          // 2*H
#define KO 1152          // H + P

#define CHUNKS 64        // L-splits for attention
#define LC (L / CHUNKS)  // 32
#define PS (H + 4)       // partial stride (16B aligned)

typedef unsigned long long U64;

union U64F2 { U64 u; float2 f; };

__device__ __forceinline__ U64 fma2(U64 a, U64 b, U64 c) {
    U64 d;
    asm("fma.rn.f32x2 %0, %1, %2, %3;" : "=l"(d) : "l"(a), "l"(b), "l"(c));
    return d;
}
__device__ __forceinline__ U64 mul2(U64 a, U64 b) {
    U64 d;
    asm("mul.rn.f32x2 %0, %1, %2;" : "=l"(d) : "l"(a), "l"(b));
    return d;
}
__device__ __forceinline__ float hsum2(U64 a) {
    U64F2 t; t.u = a; return t.f.x + t.f.y;
}
__device__ __forceinline__ U64 dup2(float x) {
    U64F2 t; t.f.x = x; t.f.y = x; return t.u;
}
__device__ __forceinline__ U64 pack2(float x, float y) {
    U64F2 t; t.f.x = x; t.f.y = y; return t.u;
}
// pack two floats to half2: lo = x (even k), hi = y
__device__ __forceinline__ uint32_t f2h2(float x, float y) {
    uint32_t r;
    asm("cvt.rn.f16x2.f32 %0, %1, %2;" : "=r"(r) : "f"(y), "f"(x));
    return r;
}
__device__ __forceinline__ uint32_t smem_u32(const void* p) {
    uint32_t a;
    asm("{ .reg .u64 t; cvta.to.shared.u64 t, %1; cvt.u32.u64 %0, t; }"
        : "=r"(a) : "l"(p));
    return a;
}

#define CP_ASYNC16(dst, src) \
    asm volatile("cp.async.cg.shared.global [%0], [%1], 16;" \
                 :: "r"(dst), "l"(src) : "memory")
#define CP_COMMIT  asm volatile("cp.async.commit_group;" ::: "memory")
#define CP_WAIT_1  asm volatile("cp.async.wait_group 1;" ::: "memory")
#define CP_WAIT_0  asm volatile("cp.async.wait_group 0;" ::: "memory")

// Scratch (device globals — no allocation allowed)
__device__ float g_hnew[B * H];
__device__ float g_cat[B * H2];                 // [h_new | context]
__device__ float g_catp[B * KO];                // [concat_out | prior]
__device__ float g_energy[B * L];
__device__ float g_part[B * CHUNKS * PS];       // ctx partial + (m, s)
__device__ float g_pih[4 * B * 3 * H];          // GRU ih partials (ksplit=4)
__device__ float g_phh[4 * B * 3 * H];          // GRU hh partials
__device__ float g_pcc[16 * B * H];             // concat partials (ksplit=16)

// ---------------------------------------------------------------------------
// SIMT GEMM (GRU + concat): C[b,n] = sum_k A[b,k]*W[n,k]
// Optional row indirection for A0 (embedding gather folded in).
// ---------------------------------------------------------------------------
#define GKT 32

__global__ void __launch_bounds__(256)
gemm_kernel(const float* __restrict__ A0, const float* __restrict__ A1,
            const float* __restrict__ W0, const float* __restrict__ W1,
            float* __restrict__ C0, float* __restrict__ C1,
            const float* __restrict__ bias,
            int N, int K, int ksplit, int ldc,
            const int* __restrict__ gidx)     // if non-null: A0 rows = A0 + gidx[r]*K
{
    __shared__ U64 As2[16][66];
    __shared__ U64 Ws2[16][130];

    const float* A = blockIdx.z ? A1 : A0;
    const float* W = blockIdx.z ? W1 : W0;
    float*       C = blockIdx.z ? C1 : C0;
    bool use_g = (gidx != nullptr) && (blockIdx.z == 0);

    int vbase = blockIdx.x * 128;
    int kc    = K / ksplit;
    int k0    = blockIdx.y * kc;
    int tiles = kc / GKT;

    int tid = threadIdx.x;
    int vg  = tid >> 4;
    int bg  = tid & 15;
    int r8  = tid >> 3;
    int k4  = tid & 7;

    const float* arow[2];
    #pragma unroll
    for (int i = 0; i < 2; i++) {
        int r = r8 + i * 32;
        size_t ro = use_g ? (size_t)__ldg(&gidx[r]) : (size_t)r;
        arow[i] = A + ro * K;
    }

    U64 acc[8][4];
    #pragma unroll
    for (int v = 0; v < 8; v++)
        #pragma unroll
        for (int j = 0; j < 4; j++) acc[v][j] = 0ull;

    float4 pa[2], pw[4];
    {
        int kt = k0 + k4 * 4;
        #pragma unroll
        for (int i = 0; i < 2; i++)
            pa[i] = *(const float4*)(arow[i] + kt);
        #pragma unroll
        for (int i = 0; i < 4; i++)
            pw[i] = *(const float4*)(W + (size_t)(vbase + r8 + i * 32) * K + kt);
    }

    for (int t = 0; t < tiles; t++) {
        __syncthreads();
        #pragma unroll
        for (int i = 0; i < 2; i++) {
            int b = r8 + i * 32;
            As2[2 * k4][b]     = pack2(pa[i].x, pa[i].y);
            As2[2 * k4 + 1][b] = pack2(pa[i].z, pa[i].w);
        }
        #pragma unroll
        for (int i = 0; i < 4; i++) {
            int n = r8 + i * 32;
            Ws2[2 * k4][n]     = pack2(pw[i].x, pw[i].y);
            Ws2[2 * k4 + 1][n] = pack2(pw[i].z, pw[i].w);
        }
        __syncthreads();

        if (t + 1 < tiles) {
            int kt = k0 + (t + 1) * GKT + k4 * 4;
            #pragma unroll
            for (int i = 0; i < 2; i++)
                pa[i] = *(const float4*)(arow[i] + kt);
            #pragma unroll
            for (int i = 0; i < 4; i++)
                pw[i] = *(const float4*)(W + (size_t)(vbase + r8 + i * 32) * K + kt);
        }

        #pragma unroll
        for (int kp = 0; kp < 16; kp++) {
            ulonglong2 a01 = *(const ulonglong2*)&As2[kp][bg * 4];
            ulonglong2 a23 = *(const ulonglong2*)&As2[kp][bg * 4 + 2];
            ulonglong2 w01 = *(const ulonglong2*)&Ws2[kp][vg * 8];
            ulonglong2 w23 = *(const ulonglong2*)&Ws2[kp][vg * 8 + 2];
            ulonglong2 w45 = *(const ulonglong2*)&Ws2[kp][vg * 8 + 4];
            ulonglong2 w67 = *(const ulonglong2*)&Ws2[kp][vg * 8 + 6];
            U64 a[4] = {a01.x, a01.y, a23.x, a23.y};
            U64 w[8] = {w01.x, w01.y, w23.x, w23.y, w45.x, w45.y, w67.x, w67.y};
            #pragma unroll
            for (int v = 0; v < 8; v++) {
                acc[v][0] = fma2(a[0], w[v], acc[v][0]);
                acc[v][1] = fma2(a[1], w[v], acc[v][1]);
                acc[v][2] = fma2(a[2], w[v], acc[v][2]);
                acc[v][3] = fma2(a[3], w[v], acc[v][3]);
            }
        }
    }

    float bv[8];
    #pragma unroll
    for (int v = 0; v < 8; v++)
        bv[v] = bias ? bias[vbase + vg * 8 + v] : 0.0f;

    float* Cb = bias ? C : (C + (size_t)blockIdx.y * 64 * ldc);
    #pragma unroll
    for (int j = 0; j < 4; j++) {
        int b = bg * 4 + j;
        float4 o0, o1;
        o0.x = hsum2(acc[0][j]) + bv[0];
        o0.y = hsum2(acc[1][j]) + bv[1];
        o0.z = hsum2(acc[2][j]) + bv[2];
        o0.w = hsum2(acc[3][j]) + bv[3];
        o1.x = hsum2(acc[4][j]) + bv[4];
        o1.y = hsum2(acc[5][j]) + bv[5];
        o1.z = hsum2(acc[6][j]) + bv[6];
        o1.w = hsum2(acc[7][j]) + bv[7];
        float* cp = Cb + (size_t)b * ldc + vbase + vg * 8;
        *(float4*)cp       = o0;
        *(float4*)(cp + 4) = o1;
    }
}

// ---------------------------------------------------------------------------
// GRU gates
// ---------------------------------------------------------------------------
__global__ void gru_gates_kernel(const float* __restrict__ lh,
                                 const float* __restrict__ bih,
                                 const float* __restrict__ bhh,
                                 float* __restrict__ out_h)
{
    int idx = blockIdx.x * 256 + threadIdx.x;
    int b = idx >> 10;
    int c = idx & 1023;

    float gir = 0.f, giz = 0.f, gin = 0.f, ghr = 0.f, ghz = 0.f, ghn = 0.f;
    #pragma unroll
    for (int s = 0; s < 4; s++) {
        size_t base = ((size_t)(s * 64 + b)) * (3 * H) + c;
        gir += g_pih[base];
        giz += g_pih[base + H];
        gin += g_pih[base + 2 * H];
        ghr += g_phh[base];
        ghz += g_phh[base + H];
        ghn += g_phh[base + 2 * H];
    }
    gir += bih[c]; giz += bih[c + H]; gin += bih[c + 2 * H];
    ghr += bhh[c]; ghz += bhh[c + H]; ghn += bhh[c + 2 * H];

    float r = 1.0f / (1.0f + expf(-(gir + ghr)));
    float z = 1.0f / (1.0f + expf(-(giz + ghz)));
    float n = tanhf(gin + r * ghn);
    float hp = lh[(size_t)b * H + c];
    float hn = (1.0f - z) * n + z * hp;

    g_hnew[(size_t)b * H + c] = hn;
    g_cat[(size_t)b * H2 + c] = hn;
    if (out_h) out_h[(size_t)b * H + c] = hn;
}

// ---------------------------------------------------------------------------
// concat reduce
// ---------------------------------------------------------------------------
__global__ void creduce_kernel(const float* __restrict__ bc)
{
    int idx = blockIdx.x * 256 + threadIdx.x;
    int b = idx >> 10;
    int c = idx & 1023;
    float s = 0.f;
    #pragma unroll
    for (int k = 0; k < 16; k++)
        s += g_pcc[((size_t)(k * 64 + b)) * H + c];
    g_catp[(size_t)b * KO + c] = tanhf(s + bc[c]);
}

// ---------------------------------------------------------------------------
// Attention pass 1: cp.async 2-stage pipelined flash attention (R8 version).
// ---------------------------------------------------------------------------
extern __shared__ float attn_smem[];   // 4 warps * 2 stages * 2 rows * H floats

__global__ void __launch_bounds__(128)
attn1_kernel(const float* __restrict__ enc)
{
    int warp = threadIdx.x >> 5;
    int lane = threadIdx.x & 31;
    int gw   = blockIdx.x * 4 + warp;
    int b    = gw >> 6;
    int ch   = gw & 63;
    int l0   = ch * LC;

    uint32_t wbase = smem_u32(attn_smem) + warp * 16384u;
    float*   wptr  = attn_smem + warp * 4096;

    U64 q[16];
    {
        const float* qp = g_hnew + (size_t)b * H;
        #pragma unroll
        for (int j = 0; j < 8; j++) {
            ulonglong2 v = *(const ulonglong2*)(qp + j * 128 + lane * 4);
            q[2 * j] = v.x; q[2 * j + 1] = v.y;
        }
    }

    U64 cacc[16];
    #pragma unroll
    for (int i = 0; i < 16; i++) cacc[i] = 0ull;
    float m = -1e30f, s = 0.0f;

    {
        const float* eg0 = enc + ((size_t)l0 * B + b) * H + lane * 4;
        uint32_t d0 = wbase + lane * 16u;
        #pragma unroll
        for (int j = 0; j < 8; j++) {
            CP_ASYNC16(d0 + j * 512u,          eg0 + j * 128);
            CP_ASYNC16(d0 + 4096u + j * 512u,  eg0 + (size_t)B * H + j * 128);
        }
        CP_COMMIT;
    }

    #pragma unroll 1
    for (int i = 0; i < LC / 2; i++) {
        int stage = i & 1;

        if (i + 1 < LC / 2) {
            const float* eg0 = enc + ((size_t)(l0 + 2 * (i + 1)) * B + b) * H + lane * 4;
            uint32_t d0 = wbase + (uint32_t)((stage ^ 1) * 8192) + lane * 16u;
            #pragma unroll
            for (int j = 0; j < 8; j++) {
                CP_ASYNC16(d0 + j * 512u,          eg0 + j * 128);
                CP_ASYNC16(d0 + 4096u + j * 512u,  eg0 + (size_t)B * H + j * 128);
            }
            CP_COMMIT;
            CP_WAIT_1;
        } else {
            CP_WAIT_0;
        }

        const float* sb = wptr + stage * 2048 + lane * 4;
        U64 ev0[16], ev1[16];
        #pragma unroll
        for (int j = 0; j < 8; j++) {
            ulonglong2 v0 = *(const ulonglong2*)(sb + j * 128);
            ulonglong2 v1 = *(const ulonglong2*)(sb + 1024 + j * 128);
            ev0[2 * j] = v0.x; ev0[2 * j + 1] = v0.y;
            ev1[2 * j] = v1.x; ev1[2 * j + 1] = v1.y;
        }

        U64 ea0 = 0ull, ea1 = 0ull;
        #pragma unroll
        for (int k = 0; k < 16; k++) {
            ea0 = fma2(ev0[k], q[k], ea0);
            ea1 = fma2(ev1[k], q[k], ea1);
        }
        float e0 = hsum2(ea0);
        float e1 = hsum2(ea1);
        #pragma unroll
        for (int off = 16; off > 0; off >>= 1) {
            e0 += __shfl_xor_sync(0xffffffffu, e0, off);
            e1 += __shfl_xor_sync(0xffffffffu, e1, off);
        }

        if (lane == 0) {
            g_energy[(size_t)b * L + l0 + 2 * i]     = e0;
            g_energy[(size_t)b * L + l0 + 2 * i + 1] = e1;
        }

        float mn = fmaxf(m, fmaxf(e0, e1));
        float sc = expf(m - mn);
        float p0 = expf(e0 - mn);
        float p1 = expf(e1 - mn);
        s = s * sc + p0 + p1;
        m = mn;
        U64 sc2 = dup2(sc), pp0 = dup2(p0), pp1 = dup2(p1);
        #pragma unroll
        for (int k = 0; k < 16; k++) {
            U64 t = mul2(cacc[k], sc2);
            t = fma2(ev0[k], pp0, t);
            cacc[k] = fma2(ev1[k], pp1, t);
        }
    }

    float* pb = g_part + (size_t)(b * CHUNKS + ch) * PS;
    #pragma unroll
    for (int j = 0; j < 8; j++) {
        ulonglong2 w;
        w.x = cacc[2 * j]; w.y = cacc[2 * j + 1];
        *(ulonglong2*)(pb + j * 128 + lane * 4) = w;
    }
    if (lane == 0) { pb[H] = m; pb[H + 1] = s; }
}

// ---------------------------------------------------------------------------
// Combine partials — parallelized: grid (B, 4). Each block handles a 256-wide
// h-slice of the context for batch b (plus 1/4 of the attn-weight writes).
// ---------------------------------------------------------------------------
__global__ void __launch_bounds__(256)
combine_kernel(const float* __restrict__ prior,
               float* __restrict__ out, int write_attn)
{
    int b  = blockIdx.x;
    int sl = blockIdx.y;
    int t  = threadIdx.x;

    __shared__ float shm[CHUNKS], shs[CHUNKS], shw[CHUNKS];
    __shared__ float shM, shS;

    if (t < CHUNKS) {
        shm[t] = g_part[(size_t)(b * CHUNKS + t) * PS + H];
        shs[t] = g_part[(size_t)(b * CHUNKS + t) * PS + H + 1];
    }
    __syncthreads();
    if (t < 32) {
        float M = fmaxf(shm[t], shm[t + 32]);
        #pragma unroll
        for (int off = 16; off > 0; off >>= 1)
            M = fmaxf(M, __shfl_xor_sync(0xffffffffu, M, off));
        if (t == 0) shM = M;
    }
    __syncthreads();
    float M = shM;
    if (t < CHUNKS) shw[t] = expf(shm[t] - M);
    __syncthreads();
    if (t < 32) {
        float S = shs[t] * shw[t] + shs[t + 32] * shw[t + 32];
        #pragma unroll
        for (int off = 16; off > 0; off >>= 1)
            S += __shfl_xor_sync(0xffffffffu, S, off);
        if (t == 0) shS = S;
    }
    __syncthreads();
    float invS = 1.0f / shS;

    // context slice: h = sl*256 + t (one float per thread, coalesced)
    {
        int h = sl * 256 + t;
        const float* pp = g_part + (size_t)b * CHUNKS * PS + h;
        float acc = 0.f;
        #pragma unroll 8
        for (int i = 0; i < CHUNKS; i++)
            acc += shw[i] * pp[(size_t)i * PS];
        g_cat[(size_t)b * H2 + H + h] = acc * invS;
    }

    if (write_attn) {
        size_t base = (size_t)B * V + (size_t)B * H + (size_t)b * L;
        int l0 = sl * (L / 4);
        for (int l = l0 + t; l < l0 + L / 4; l += 256)
            out[base + l] = expf(g_energy[(size_t)b * L + l] - M) * invS;
    }

    if (sl == 0 && t < P)
        g_catp[(size_t)b * KO + H + t] = prior[(size_t)b * P + t];
}

// ---------------------------------------------------------------------------
// Output GEMM via mma.sync fp16 (m16n8k16) — round-8 version (known good).
// Block = 128v x 64b, 8 warps (2x4), warp tile 64m x 16n. K-tiles of 32,
// double-buffered static smem, one sync per tile. HSTRIDE 20 -> conflict-free.
// ---------------------------------------------------------------------------
#define OKT 32
#define OTILES (KO / OKT)   // 36
#define HSTRIDE 20          // half2 per row

__device__ __forceinline__ void mma_f16(float* d, uint32_t a0, uint32_t a1,
                                        uint32_t a2, uint32_t a3,
                                        uint32_t b0, uint32_t b1)
{
    asm volatile(
        "mma.sync.aligned.m16n8k16.row.col.f32.f16.f16.f32 "
        "{%0,%1,%2,%3}, {%4,%5,%6,%7}, {%8,%9}, {%0,%1,%2,%3};"
        : "+f"(d[0]), "+f"(d[1]), "+f"(d[2]), "+f"(d[3])
        : "r"(a0), "r"(a1), "r"(a2), "r"(a3), "r"(b0), "r"(b1));
}

__global__ void __launch_bounds__(256, 2)
out_gemm_tc_kernel(const float* __restrict__ Wout,
                   const float* __restrict__ bout,
                   float* __restrict__ outp)
{
    __shared__ uint32_t A_h[2][128 * HSTRIDE];  // 2 x 10 KB (half2)
    __shared__ uint32_t B_h[2][64 * HSTRIDE];   // 2 x 5 KB

    int tid   = threadIdx.x;
    int wid   = tid >> 5;
    int lane  = tid & 31;
    int gid   = lane >> 2;
    int tig   = lane & 3;
    int vbase = blockIdx.x * 128;

    int warp_m = wid & 1;
    int warp_n = wid >> 1;
    int mbase  = warp_m * 64;
    int nbase  = warp_n * 16;

    int arow = tid >> 3;     // 0..31 (+32k)
    int ac4  = tid & 7;

    float acc[4][2][4];
    #pragma unroll
    for (int mt = 0; mt < 4; mt++)
        #pragma unroll
        for (int nt = 0; nt < 2; nt++)
            #pragma unroll
            for (int i = 0; i < 4; i++) acc[mt][nt][i] = 0.0f;

    float4 pa[4], pb[2];

    // prologue: load tile 0, store to buffer 0
    #pragma unroll
    for (int j = 0; j < 4; j++) {
        int row = arow + j * 32;
        pa[j] = *(const float4*)(Wout + (size_t)(vbase + row) * KO + ac4 * 4);
    }
    #pragma unroll
    for (int j = 0; j < 2; j++) {
        int row = arow + j * 32;
        pb[j] = *(const float4*)(g_catp + (size_t)row * KO + ac4 * 4);
    }
    #pragma unroll
    for (int j = 0; j < 4; j++) {
        int row = arow + j * 32;
        *(uint2*)&A_h[0][row * HSTRIDE + ac4 * 2] =
            make_uint2(f2h2(pa[j].x, pa[j].y), f2h2(pa[j].z, pa[j].w));
    }
    #pragma unroll
    for (int j = 0; j < 2; j++) {
        int row = arow + j * 32;
        *(uint2*)&B_h[0][row * HSTRIDE + ac4 * 2] =
            make_uint2(f2h2(pb[j].x, pb[j].y), f2h2(pb[j].z, pb[j].w));
    }

    #pragma unroll 1
    for (int t = 0; t < OTILES; t++) {
        __syncthreads();   // buf[t&1] ready; all warps done reading buf[(t+1)&1]
        int buf = t & 1;

        if (t + 1 < OTILES) {
            int kt = (t + 1) * OKT;
            #pragma unroll
            for (int j = 0; j < 4; j++) {
                int row = arow + j * 32;
                pa[j] = *(const float4*)(Wout + (size_t)(vbase + row) * KO + kt + ac4 * 4);
            }
            #pragma unroll
            for (int j = 0; j < 2; j++) {
                int row = arow + j * 32;
                pb[j] = *(const float4*)(g_catp + (size_t)row * KO + kt + ac4 * 4);
            }
        }

        // MMA over buf: 2 k16 chunks per 32-k tile
        #pragma unroll
        for (int kb = 0; kb < 2; kb++) {
            int k2 = kb * 8 + tig;

            uint32_t bf0[2], bf1[2];
            #pragma unroll
            for (int nt = 0; nt < 2; nt++) {
                int n0 = nbase + nt * 8 + gid;
                bf0[nt] = B_h[buf][n0 * HSTRIDE + k2];
                bf1[nt] = B_h[buf][n0 * HSTRIDE + k2 + 4];
            }
            #pragma unroll
            for (int mt = 0; mt < 4; mt++) {
                int r0 = mbase + mt * 16 + gid;
                uint32_t a0 = A_h[buf][r0 * HSTRIDE + k2];
                uint32_t a1 = A_h[buf][(r0 + 8) * HSTRIDE + k2];
                uint32_t a2 = A_h[buf][r0 * HSTRIDE + k2 + 4];
                uint32_t a3 = A_h[buf][(r0 + 8) * HSTRIDE + k2 + 4];
                mma_f16(acc[mt][0], a0, a1, a2, a3, bf0[0], bf1[0]);
                mma_f16(acc[mt][1], a0, a1, a2, a3, bf0[1], bf1[1]);
            }
        }

        if (t + 1 < OTILES) {
            int nbuf = buf ^ 1;
            #pragma unroll
            for (int j = 0; j < 4; j++) {
                int row = arow + j * 32;
                *(uint2*)&A_h[nbuf][row * HSTRIDE + ac4 * 2] =
                    make_uint2(f2h2(pa[j].x, pa[j].y), f2h2(pa[j].z, pa[j].w));
            }
            #pragma unroll
            for (int j = 0; j < 2; j++) {
                int row = arow + j * 32;
                *(uint2*)&B_h[nbuf][row * HSTRIDE + ac4 * 2] =
                    make_uint2(f2h2(pb[j].x, pb[j].y), f2h2(pb[j].z, pb[j].w));
            }
        }
    }

    // epilogue: D[v, b] -> outp[b*V + v] + bias[v]
    #pragma unroll
    for (int mt = 0; mt < 4; mt++) {
        int v0 = vbase + mbase + mt * 16 + gid;
        float bias0 = bout[v0];
        float bias1 = bout[v0 + 8];
        #pragma unroll
        for (int nt = 0; nt < 2; nt++) {
            int bcol = nbase + nt * 8 + 2 * tig;
            outp[(size_t)bcol * V + v0]           = acc[mt][nt][0] + bias0;
            outp[(size_t)(bcol + 1) * V + v0]     = acc[mt][nt][1] + bias0;
            outp[(size_t)bcol * V + v0 + 8]       = acc[mt][nt][2] + bias1;
            outp[(size_t)(bcol + 1) * V + v0 + 8] = acc[mt][nt][3] + bias1;
        }
    }
}

// ---------------------------------------------------------------------------
extern "C" void kernel_launch(void* const* d_in, const int* in_sizes, int n_in,
                              void* d_out, int out_size)
{
    const int*   seq   = (const int*)d_in[0];   // int32 (JAX x64 disabled)
    const float* lh    = (const float*)d_in[1];
    const float* enc   = (const float*)d_in[2];
    const float* prior = (const float*)d_in[3];
    const float* emb   = (const float*)d_in[4];
    const float* Wih   = (const float*)d_in[5];
    const float* Whh   = (const float*)d_in[6];
    const float* bih   = (const float*)d_in[7];
    const float* bhh   = (const float*)d_in[8];
    const float* Wc    = (const float*)d_in[9];
    const float* bc    = (const float*)d_in[10];
    const float* Wout  = (const float*)d_in[11];
    const float* bout  = (const float*)d_in[12];

    float* out = (float*)d_out;
    long long need_h    = (long long)B * V + (long long)B * H;
    long long need_attn = need_h + (long long)B * L;
    float* out_h = ((long long)out_size >= need_h) ? out + (size_t)B * V : nullptr;
    int write_attn = ((long long)out_size >= need_attn) ? 1 : 0;

    float* pih; cudaGetSymbolAddress((void**)&pih, g_pih);
    float* phh; cudaGetSymbolAddress((void**)&phh, g_phh);
    float* pcc; cudaGetSymbolAddress((void**)&pcc, g_pcc);
    float* gcat; cudaGetSymbolAddress((void**)&gcat, g_cat);

    cudaFuncSetAttribute(attn1_kernel,
                         cudaFuncAttributeMaxDynamicSharedMemorySize, 65536);

    // 1. GRU GEMMs: gi = emb[seq]@Wih^T (gather folded in), gh = h@Whh^T
    gemm_kernel<<<dim3(3 * H / 128, 4, 2), 256>>>(
        emb, lh, Wih, Whh, pih, phh, nullptr, 3 * H, H, 4, 3 * H, seq);

    // 2. gates -> h_new
    gru_gates_kernel<<<B * H / 256, 256>>>(lh, bih, bhh, out_h);

    // 3. flash attention over encoder_outputs (read once, 2-stage cp.async)
    attn1_kernel<<<B * CHUNKS / 4, 128, 65536>>>(enc);

    // 4. combine -> context, attn weights, prior copy (parallel over (B,4))
    combine_kernel<<<dim3(B, 4), 256>>>(prior, out, write_attn);

    // 5. concat GEMM (N=1024, K=2048, ksplit=16) + reduce/tanh
    gemm_kernel<<<dim3(H / 128, 16, 1), 256>>>(
        gcat, gcat, Wc, Wc, pcc, pcc, nullptr, H, H2, 16, H, nullptr);
    creduce_kernel<<<B * H / 256, 256>>>(bc);

    // 6. output GEMM (N=32000, K=1152) via mma.sync fp16 (R8 config)
    out_gemm_tc_kernel<<<V / 128, 256>>>(Wout, bout, out);
}

// round 12
// speedup vs baseline: 1.2267x; 1.0287x over previous
#include <cuda_runtime.h>
#include <cuda_bf16.h>
#include <math.h>
#include <stdint.h>

// Problem constants
#define B  64
#define L  2048
#define H  1024
#define V  32000
#define P  128
#define H2 2048          // 2*H
#define KO 1152          // H + P

#define CHUNKS 32        // L-splits for attention
#define LC (L / CHUNKS)  // 64
#define PS (H + 4)       // partial stride (16B aligned)

typedef unsigned long long U64;

union U64F2 { U64 u; float2 f; };

__device__ __forceinline__ U64 fma2(U64 a, U64 b, U64 c) {
    U64 d;
    asm("fma.rn.f32x2 %0, %1, %2, %3;" : "=l"(d) : "l"(a), "l"(b), "l"(c));
    return d;
}
__device__ __forceinline__ U64 mul2(U64 a, U64 b) {
    U64 d;
    asm("mul.rn.f32x2 %0, %1, %2;" : "=l"(d) : "l"(a), "l"(b));
    return d;
}
__device__ __forceinline__ float hsum2(U64 a) {
    U64F2 t; t.u = a; return t.f.x + t.f.y;
}
__device__ __forceinline__ U64 dup2(float x) {
    U64F2 t; t.f.x = x; t.f.y = x; return t.u;
}
__device__ __forceinline__ U64 pack2(float x, float y) {
    U64F2 t; t.f.x = x; t.f.y = y; return t.u;
}
// pack two floats to half2: lo = x (even k), hi = y
__device__ __forceinline__ uint32_t f2h2(float x, float y) {
    uint32_t r;
    asm("cvt.rn.f16x2.f32 %0, %1, %2;" : "=r"(r) : "f"(y), "f"(x));
    return r;
}
__device__ __forceinline__ uint32_t smem_u32(const void* p) {
    uint32_t a;
    asm("{ .reg .u64 t; cvta.to.shared.u64 t, %1; cvt.u32.u64 %0, t; }"
        : "=r"(a) : "l"(p));
    return a;
}

#define CP_ASYNC16(dst, src) \
    asm volatile("cp.async.cg.shared.global [%0], [%1], 16;" \
                 :: "r"(dst), "l"(src) : "memory")
#define CP_COMMIT  asm volatile("cp.async.commit_group;" ::: "memory")
#define CP_WAIT_1  asm volatile("cp.async.wait_group 1;" ::: "memory")
#define CP_WAIT_0  asm volatile("cp.async.wait_group 0;" ::: "memory")

// Scratch (device globals — no allocation allowed)
__device__ float g_hnew[B * H];
__device__ float g_cat[B * H2];                 // [h_new | context]
__device__ float g_catp[B * KO];                // [concat_out | prior]
__device__ float g_energy[B * L];
__device__ float g_part[B * CHUNKS * PS];       // ctx partial + (m, s)
__device__ float g_pih[4 * B * 3 * H];          // GRU ih partials (ksplit=4)
__device__ float g_phh[4 * B * 3 * H];          // GRU hh partials
__device__ float g_pcc[16 * B * H];             // concat partials (ksplit=16)

// ---------------------------------------------------------------------------
// SIMT GEMM (GRU + concat): C[b,n] = sum_k A[b,k]*W[n,k]
// Optional row indirection for A0 (embedding gather folded in).
// ---------------------------------------------------------------------------
#define GKT 32

__global__ void __launch_bounds__(256)
gemm_kernel(const float* __restrict__ A0, const float* __restrict__ A1,
            const float* __restrict__ W0, const float* __restrict__ W1,
            float* __restrict__ C0, float* __restrict__ C1,
            const float* __restrict__ bias,
            int N, int K, int ksplit, int ldc,
            const int* __restrict__ gidx)     // if non-null: A0 rows = A0 + gidx[r]*K
{
    __shared__ U64 As2[16][66];
    __shared__ U64 Ws2[16][130];

    const float* A = blockIdx.z ? A1 : A0;
    const float* W = blockIdx.z ? W1 : W0;
    float*       C = blockIdx.z ? C1 : C0;
    bool use_g = (gidx != nullptr) && (blockIdx.z == 0);

    int vbase = blockIdx.x * 128;
    int kc    = K / ksplit;
    int k0    = blockIdx.y * kc;
    int tiles = kc / GKT;

    int tid = threadIdx.x;
    int vg  = tid >> 4;
    int bg  = tid & 15;
    int r8  = tid >> 3;
    int k4  = tid & 7;

    const float* arow[2];
    #pragma unroll
    for (int i = 0; i < 2; i++) {
        int r = r8 + i * 32;
        size_t ro = use_g ? (size_t)__ldg(&gidx[r]) : (size_t)r;
        arow[i] = A + ro * K;
    }

    U64 acc[8][4];
    #pragma unroll
    for (int v = 0; v < 8; v++)
        #pragma unroll
        for (int j = 0; j < 4; j++) acc[v][j] = 0ull;

    float4 pa[2], pw[4];
    {
        int kt = k0 + k4 * 4;
        #pragma unroll
        for (int i = 0; i < 2; i++)
            pa[i] = *(const float4*)(arow[i] + kt);
        #pragma unroll
        for (int i = 0; i < 4; i++)
            pw[i] = *(const float4*)(W + (size_t)(vbase + r8 + i * 32) * K + kt);
    }

    for (int t = 0; t < tiles; t++) {
        __syncthreads();
        #pragma unroll
        for (int i = 0; i < 2; i++) {
            int b = r8 + i * 32;
            As2[2 * k4][b]     = pack2(pa[i].x, pa[i].y);
            As2[2 * k4 + 1][b] = pack2(pa[i].z, pa[i].w);
        }
        #pragma unroll
        for (int i = 0; i < 4; i++) {
            int n = r8 + i * 32;
            Ws2[2 * k4][n]     = pack2(pw[i].x, pw[i].y);
            Ws2[2 * k4 + 1][n] = pack2(pw[i].z, pw[i].w);
        }
        __syncthreads();

        if (t + 1 < tiles) {
            int kt = k0 + (t + 1) * GKT + k4 * 4;
            #pragma unroll
            for (int i = 0; i < 2; i++)
                pa[i] = *(const float4*)(arow[i] + kt);
            #pragma unroll
            for (int i = 0; i < 4; i++)
                pw[i] = *(const float4*)(W + (size_t)(vbase + r8 + i * 32) * K + kt);
        }

        #pragma unroll
        for (int kp = 0; kp < 16; kp++) {
            ulonglong2 a01 = *(const ulonglong2*)&As2[kp][bg * 4];
            ulonglong2 a23 = *(const ulonglong2*)&As2[kp][bg * 4 + 2];
            ulonglong2 w01 = *(const ulonglong2*)&Ws2[kp][vg * 8];
            ulonglong2 w23 = *(const ulonglong2*)&Ws2[kp][vg * 8 + 2];
            ulonglong2 w45 = *(const ulonglong2*)&Ws2[kp][vg * 8 + 4];
            ulonglong2 w67 = *(const ulonglong2*)&Ws2[kp][vg * 8 + 6];
            U64 a[4] = {a01.x, a01.y, a23.x, a23.y};
            U64 w[8] = {w01.x, w01.y, w23.x, w23.y, w45.x, w45.y, w67.x, w67.y};
            #pragma unroll
            for (int v = 0; v < 8; v++) {
                acc[v][0] = fma2(a[0], w[v], acc[v][0]);
                acc[v][1] = fma2(a[1], w[v], acc[v][1]);
                acc[v][2] = fma2(a[2], w[v], acc[v][2]);
                acc[v][3] = fma2(a[3], w[v], acc[v][3]);
            }
        }
    }

    float bv[8];
    #pragma unroll
    for (int v = 0; v < 8; v++)
        bv[v] = bias ? bias[vbase + vg * 8 + v] : 0.0f;

    float* Cb = bias ? C : (C + (size_t)blockIdx.y * 64 * ldc);
    #pragma unroll
    for (int j = 0; j < 4; j++) {
        int b = bg * 4 + j;
        float4 o0, o1;
        o0.x = hsum2(acc[0][j]) + bv[0];
        o0.y = hsum2(acc[1][j]) + bv[1];
        o0.z = hsum2(acc[2][j]) + bv[2];
        o0.w = hsum2(acc[3][j]) + bv[3];
        o1.x = hsum2(acc[4][j]) + bv[4];
        o1.y = hsum2(acc[5][j]) + bv[5];
        o1.z = hsum2(acc[6][j]) + bv[6];
        o1.w = hsum2(acc[7][j]) + bv[7];
        float* cp = Cb + (size_t)b * ldc + vbase + vg * 8;
        *(float4*)cp       = o0;
        *(float4*)(cp + 4) = o1;
    }
}

// ---------------------------------------------------------------------------
// GRU gates
// ---------------------------------------------------------------------------
__global__ void gru_gates_kernel(const float* __restrict__ lh,
                                 const float* __restrict__ bih,
                                 const float* __restrict__ bhh,
                                 float* __restrict__ out_h)
{
    int idx = blockIdx.x * 256 + threadIdx.x;
    int b = idx >> 10;
    int c = idx & 1023;

    float gir = 0.f, giz = 0.f, gin = 0.f, ghr = 0.f, ghz = 0.f, ghn = 0.f;
    #pragma unroll
    for (int s = 0; s < 4; s++) {
        size_t base = ((size_t)(s * 64 + b)) * (3 * H) + c;
        gir += g_pih[base];
        giz += g_pih[base + H];
        gin += g_pih[base + 2 * H];
        ghr += g_phh[base];
        ghz += g_phh[base + H];
        ghn += g_phh[base + 2 * H];
    }
    gir += bih[c]; giz += bih[c + H]; gin += bih[c + 2 * H];
    ghr += bhh[c]; ghz += bhh[c + H]; ghn += bhh[c + 2 * H];

    float r = 1.0f / (1.0f + expf(-(gir + ghr)));
    float z = 1.0f / (1.0f + expf(-(giz + ghz)));
    float n = tanhf(gin + r * ghn);
    float hp = lh[(size_t)b * H + c];
    float hn = (1.0f - z) * n + z * hp;

    g_hnew[(size_t)b * H + c] = hn;
    g_cat[(size_t)b * H2 + c] = hn;
    if (out_h) out_h[(size_t)b * H + c] = hn;
}

// ---------------------------------------------------------------------------
// concat reduce
// ---------------------------------------------------------------------------
__global__ void creduce_kernel(const float* __restrict__ bc)
{
    int idx = blockIdx.x * 256 + threadIdx.x;
    int b = idx >> 10;
    int c = idx & 1023;
    float s = 0.f;
    #pragma unroll
    for (int k = 0; k < 16; k++)
        s += g_pcc[((size_t)(k * 64 + b)) * H + c];
    g_catp[(size_t)b * KO + c] = tanhf(s + bc[c]);
}

// ---------------------------------------------------------------------------
// Attention pass 1: cp.async 2-stage pipelined flash attention.
// One warp per (b, chunk); CHUNKS=32 -> LC=64 rows per warp (32 pair-iters).
// ---------------------------------------------------------------------------
extern __shared__ float attn_smem[];   // 4 warps * 2 stages * 2 rows * H floats

__global__ void __launch_bounds__(128)
attn1_kernel(const float* __restrict__ enc)
{
    int warp = threadIdx.x >> 5;
    int lane = threadIdx.x & 31;
    int gw   = blockIdx.x * 4 + warp;
    int b    = gw >> 5;    // / CHUNKS
    int ch   = gw & 31;    // % CHUNKS
    int l0   = ch * LC;

    uint32_t wbase = smem_u32(attn_smem) + warp * 16384u;
    float*   wptr  = attn_smem + warp * 4096;

    U64 q[16];
    {
        const float* qp = g_hnew + (size_t)b * H;
        #pragma unroll
        for (int j = 0; j < 8; j++) {
            ulonglong2 v = *(const ulonglong2*)(qp + j * 128 + lane * 4);
            q[2 * j] = v.x; q[2 * j + 1] = v.y;
        }
    }

    U64 cacc[16];
    #pragma unroll
    for (int i = 0; i < 16; i++) cacc[i] = 0ull;
    float m = -1e30f, s = 0.0f;

    {
        const float* eg0 = enc + ((size_t)l0 * B + b) * H + lane * 4;
        uint32_t d0 = wbase + lane * 16u;
        #pragma unroll
        for (int j = 0; j < 8; j++) {
            CP_ASYNC16(d0 + j * 512u,          eg0 + j * 128);
            CP_ASYNC16(d0 + 4096u + j * 512u,  eg0 + (size_t)B * H + j * 128);
        }
        CP_COMMIT;
    }

    #pragma unroll 1
    for (int i = 0; i < LC / 2; i++) {
        int stage = i & 1;

        if (i + 1 < LC / 2) {
            const float* eg0 = enc + ((size_t)(l0 + 2 * (i + 1)) * B + b) * H + lane * 4;
            uint32_t d0 = wbase + (uint32_t)((stage ^ 1) * 8192) + lane * 16u;
            #pragma unroll
            for (int j = 0; j < 8; j++) {
                CP_ASYNC16(d0 + j * 512u,          eg0 + j * 128);
                CP_ASYNC16(d0 + 4096u + j * 512u,  eg0 + (size_t)B * H + j * 128);
            }
            CP_COMMIT;
            CP_WAIT_1;
        } else {
            CP_WAIT_0;
        }

        const float* sb = wptr + stage * 2048 + lane * 4;
        U64 ev0[16], ev1[16];
        #pragma unroll
        for (int j = 0; j < 8; j++) {
            ulonglong2 v0 = *(const ulonglong2*)(sb + j * 128);
            ulonglong2 v1 = *(const ulonglong2*)(sb + 1024 + j * 128);
            ev0[2 * j] = v0.x; ev0[2 * j + 1] = v0.y;
            ev1[2 * j] = v1.x; ev1[2 * j + 1] = v1.y;
        }

        U64 ea0 = 0ull, ea1 = 0ull;
        #pragma unroll
        for (int k = 0; k < 16; k++) {
            ea0 = fma2(ev0[k], q[k], ea0);
            ea1 = fma2(ev1[k], q[k], ea1);
        }
        float e0 = hsum2(ea0);
        float e1 = hsum2(ea1);
        #pragma unroll
        for (int off = 16; off > 0; off >>= 1) {
            e0 += __shfl_xor_sync(0xffffffffu, e0, off);
            e1 += __shfl_xor_sync(0xffffffffu, e1, off);
        }

        if (lane == 0) {
            g_energy[(size_t)b * L + l0 + 2 * i]     = e0;
            g_energy[(size_t)b * L + l0 + 2 * i + 1] = e1;
        }

        float mn = fmaxf(m, fmaxf(e0, e1));
        float sc = expf(m - mn);
        float p0 = expf(e0 - mn);
        float p1 = expf(e1 - mn);
        s = s * sc + p0 + p1;
        m = mn;
        U64 sc2 = dup2(sc), pp0 = dup2(p0), pp1 = dup2(p1);
        #pragma unroll
        for (int k = 0; k < 16; k++) {
            U64 t = mul2(cacc[k], sc2);
            t = fma2(ev0[k], pp0, t);
            cacc[k] = fma2(ev1[k], pp1, t);
        }
    }

    float* pb = g_part + (size_t)(b * CHUNKS + ch) * PS;
    #pragma unroll
    for (int j = 0; j < 8; j++) {
        ulonglong2 w;
        w.x = cacc[2 * j]; w.y = cacc[2 * j + 1];
        *(ulonglong2*)(pb + j * 128 + lane * 4) = w;
    }
    if (lane == 0) { pb[H] = m; pb[H + 1] = s; }
}

// ---------------------------------------------------------------------------
// Combine partials — MLP-oriented: grid (B, 4); thread (c4, g) accumulates
// 8 chunks x 1 float4 (LDG.128, all independent), reduced across the 4
// chunk-groups via smem.
// ---------------------------------------------------------------------------
__global__ void __launch_bounds__(256)
combine_kernel(const float* __restrict__ prior,
               float* __restrict__ out, int write_attn)
{
    int b  = blockIdx.x;
    int sl = blockIdx.y;
    int t  = threadIdx.x;
    int c4 = t & 63;      // float4 index within 256-float slice
    int g  = t >> 6;      // chunk group 0..3 (8 chunks each)

    __shared__ float  shm[CHUNKS], shs[CHUNKS], shw[CHUNKS];
    __shared__ float  shM, shS;
    __shared__ float4 red[4][64];

    if (t < CHUNKS) {
        shm[t] = g_part[(size_t)(b * CHUNKS + t) * PS + H];
        shs[t] = g_part[(size_t)(b * CHUNKS + t) * PS + H + 1];
    }
    __syncthreads();
    if (t < 32) {
        float M = shm[t];
        #pragma unroll
        for (int off = 16; off > 0; off >>= 1)
            M = fmaxf(M, __shfl_xor_sync(0xffffffffu, M, off));
        float w = expf(shm[t] - M);
        float S = shs[t] * w;
        #pragma unroll
        for (int off = 16; off > 0; off >>= 1)
            S += __shfl_xor_sync(0xffffffffu, S, off);
        shw[t] = w;
        if (t == 0) { shM = M; shS = S; }
    }
    __syncthreads();
    float M = shM;
    float invS = 1.0f / shS;

    // context slice: h-float4 c4 of slice sl; chunks [g*8, g*8+8)
    {
        int h = sl * 256 + c4 * 4;
        const float* pp = g_part + (size_t)b * CHUNKS * PS + h;
        float4 acc = make_float4(0.f, 0.f, 0.f, 0.f);
        #pragma unroll
        for (int i = 0; i < 8; i++) {
            int ci = g * 8 + i;
            float4 v = *(const float4*)(pp + (size_t)ci * PS);
            float w = shw[ci];
            acc.x += w * v.x; acc.y += w * v.y;
            acc.z += w * v.z; acc.w += w * v.w;
        }
        red[g][c4] = acc;
    }
    __syncthreads();

    if (t < 64) {
        float4 a0 = red[0][t], a1 = red[1][t], a2 = red[2][t], a3 = red[3][t];
        float4 o;
        o.x = (a0.x + a1.x + a2.x + a3.x) * invS;
        o.y = (a0.y + a1.y + a2.y + a3.y) * invS;
        o.z = (a0.z + a1.z + a2.z + a3.z) * invS;
        o.w = (a0.w + a1.w + a2.w + a3.w) * invS;
        *(float4*)(g_cat + (size_t)b * H2 + H + sl * 256 + t * 4) = o;
    }

    if (write_attn) {
        size_t base = (size_t)B * V + (size_t)B * H + (size_t)b * L;
        int l0 = sl * (L / 4);
        for (int l = l0 + t; l < l0 + L / 4; l += 256)
            out[base + l] = expf(g_energy[(size_t)b * L + l] - M) * invS;
    }

    if (sl == 0 && t < P)
        g_catp[(size_t)b * KO + H + t] = prior[(size_t)b * P + t];
}

// ---------------------------------------------------------------------------
// Output GEMM via mma.sync fp16 (m16n8k16) — round-8 version (known good).
// ---------------------------------------------------------------------------
#define OKT 32
#define OTILES (KO / OKT)   // 36
#define HSTRIDE 20          // half2 per row

__device__ __forceinline__ void mma_f16(float* d, uint32_t a0, uint32_t a1,
                                        uint32_t a2, uint32_t a3,
                                        uint32_t b0, uint32_t b1)
{
    asm volatile(
        "mma.sync.aligned.m16n8k16.row.col.f32.f16.f16.f32 "
        "{%0,%1,%2,%3}, {%4,%5,%6,%7}, {%8,%9}, {%0,%1,%2,%3};"
        : "+f"(d[0]), "+f"(d[1]), "+f"(d[2]), "+f"(d[3])
        : "r"(a0), "r"(a1), "r"(a2), "r"(a3), "r"(b0), "r"(b1));
}

__global__ void __launch_bounds__(256, 2)
out_gemm_tc_kernel(const float* __restrict__ Wout,
                   const float* __restrict__ bout,
                   float* __restrict__ outp)
{
    __shared__ uint32_t A_h[2][128 * HSTRIDE];  // 2 x 10 KB (half2)
    __shared__ uint32_t B_h[2][64 * HSTRIDE];   // 2 x 5 KB

    int tid   = threadIdx.x;
    int wid   = tid >> 5;
    int lane  = tid & 31;
    int gid   = lane >> 2;
    int tig   = lane & 3;
    int vbase = blockIdx.x * 128;

    int warp_m = wid & 1;
    int warp_n = wid >> 1;
    int mbase  = warp_m * 64;
    int nbase  = warp_n * 16;

    int arow = tid >> 3;     // 0..31 (+32k)
    int ac4  = tid & 7;

    float acc[4][2][4];
    #pragma unroll
    for (int mt = 0; mt < 4; mt++)
        #pragma unroll
        for (int nt = 0; nt < 2; nt++)
            #pragma unroll
            for (int i = 0; i < 4; i++) acc[mt][nt][i] = 0.0f;

    float4 pa[4], pb[2];

    #pragma unroll
    for (int j = 0; j < 4; j++) {
        int row = arow + j * 32;
        pa[j] = *(const float4*)(Wout + (size_t)(vbase + row) * KO + ac4 * 4);
    }
    #pragma unroll
    for (int j = 0; j < 2; j++) {
        int row = arow + j * 32;
        pb[j] = *(const float4*)(g_catp + (size_t)row * KO + ac4 * 4);
    }
    #pragma unroll
    for (int j = 0; j < 4; j++) {
        int row = arow + j * 32;
        *(uint2*)&A_h[0][row * HSTRIDE + ac4 * 2] =
            make_uint2(f2h2(pa[j].x, pa[j].y), f2h2(pa[j].z, pa[j].w));
    }
    #pragma unroll
    for (int j = 0; j < 2; j++) {
        int row = arow + j * 32;
        *(uint2*)&B_h[0][row * HSTRIDE + ac4 * 2] =
            make_uint2(f2h2(pb[j].x, pb[j].y), f2h2(pb[j].z, pb[j].w));
    }

    #pragma unroll 1
    for (int t = 0; t < OTILES; t++) {
        __syncthreads();
        int buf = t & 1;

        if (t + 1 < OTILES) {
            int kt = (t + 1) * OKT;
            #pragma unroll
            for (int j = 0; j < 4; j++) {
                int row = arow + j * 32;
                pa[j] = *(const float4*)(Wout + (size_t)(vbase + row) * KO + kt + ac4 * 4);
            }
            #pragma unroll
            for (int j = 0; j < 2; j++) {
                int row = arow + j * 32;
                pb[j] = *(const float4*)(g_catp + (size_t)row * KO + kt + ac4 * 4);
            }
        }

        #pragma unroll
        for (int kb = 0; kb < 2; kb++) {
            int k2 = kb * 8 + tig;

            uint32_t bf0[2], bf1[2];
            #pragma unroll
            for (int nt = 0; nt < 2; nt++) {
                int n0 = nbase + nt * 8 + gid;
                bf0[nt] = B_h[buf][n0 * HSTRIDE + k2];
                bf1[nt] = B_h[buf][n0 * HSTRIDE + k2 + 4];
            }
            #pragma unroll
            for (int mt = 0; mt < 4; mt++) {
                int r0 = mbase + mt * 16 + gid;
                uint32_t a0 = A_h[buf][r0 * HSTRIDE + k2];
                uint32_t a1 = A_h[buf][(r0 + 8) * HSTRIDE + k2];
                uint32_t a2 = A_h[buf][r0 * HSTRIDE + k2 + 4];
                uint32_t a3 = A_h[buf][(r0 + 8) * HSTRIDE + k2 + 4];
                mma_f16(acc[mt][0], a0, a1, a2, a3, bf0[0], bf1[0]);
                mma_f16(acc[mt][1], a0, a1, a2, a3, bf0[1], bf1[1]);
            }
        }

        if (t + 1 < OTILES) {
            int nbuf = buf ^ 1;
            #pragma unroll
            for (int j = 0; j < 4; j++) {
                int row = arow + j * 32;
                *(uint2*)&A_h[nbuf][row * HSTRIDE + ac4 * 2] =
                    make_uint2(f2h2(pa[j].x, pa[j].y), f2h2(pa[j].z, pa[j].w));
            }
            #pragma unroll
            for (int j = 0; j < 2; j++) {
                int row = arow + j * 32;
                *(uint2*)&B_h[nbuf][row * HSTRIDE + ac4 * 2] =
                    make_uint2(f2h2(pb[j].x, pb[j].y), f2h2(pb[j].z, pb[j].w));
            }
        }
    }

    #pragma unroll
    for (int mt = 0; mt < 4; mt++) {
        int v0 = vbase + mbase + mt * 16 + gid;
        float bias0 = bout[v0];
        float bias1 = bout[v0 + 8];
        #pragma unroll
        for (int nt = 0; nt < 2; nt++) {
            int bcol = nbase + nt * 8 + 2 * tig;
            outp[(size_t)bcol * V + v0]           = acc[mt][nt][0] + bias0;
            outp[(size_t)(bcol + 1) * V + v0]     = acc[mt][nt][1] + bias0;
            outp[(size_t)bcol * V + v0 + 8]       = acc[mt][nt][2] + bias1;
            outp[(size_t)(bcol + 1) * V + v0 + 8] = acc[mt][nt][3] + bias1;
        }
    }
}

// ---------------------------------------------------------------------------
extern "C" void kernel_launch(void* const* d_in, const int* in_sizes, int n_in,
                              void* d_out, int out_size)
{
    const int*   seq   = (const int*)d_in[0];   // int32 (JAX x64 disabled)
    const float* lh    = (const float*)d_in[1];
    const float* enc   = (const float*)d_in[2];
    const float* prior = (const float*)d_in[3];
    const float* emb   = (const float*)d_in[4];
    const float* Wih   = (const float*)d_in[5];
    const float* Whh   = (const float*)d_in[6];
    const float* bih   = (const float*)d_in[7];
    const float* bhh   = (const float*)d_in[8];
    const float* Wc    = (const float*)d_in[9];
    const float* bc    = (const float*)d_in[10];
    const float* Wout  = (const float*)d_in[11];
    const float* bout  = (const float*)d_in[12];

    float* out = (float*)d_out;
    long long need_h    = (long long)B * V + (long long)B * H;
    long long need_attn = need_h + (long long)B * L;
    float* out_h = ((long long)out_size >= need_h) ? out + (size_t)B * V : nullptr;
    int write_attn = ((long long)out_size >= need_attn) ? 1 : 0;

    float* pih; cudaGetSymbolAddress((void**)&pih, g_pih);
    float* phh; cudaGetSymbolAddress((void**)&phh, g_phh);
    float* pcc; cudaGetSymbolAddress((void**)&pcc, g_pcc);
    float* gcat; cudaGetSymbolAddress((void**)&gcat, g_cat);

    cudaFuncSetAttribute(attn1_kernel,
                         cudaFuncAttributeMaxDynamicSharedMemorySize, 65536);

    // 1. GRU GEMMs: gi = emb[seq]@Wih^T (gather folded in), gh = h@Whh^T
    gemm_kernel<<<dim3(3 * H / 128, 4, 2), 256>>>(
        emb, lh, Wih, Whh, pih, phh, nullptr, 3 * H, H, 4, 3 * H, seq);

    // 2. gates -> h_new
    gru_gates_kernel<<<B * H / 256, 256>>>(lh, bih, bhh, out_h);

    // 3. flash attention over encoder_outputs (read once, 2-stage cp.async)
    attn1_kernel<<<B * CHUNKS / 4, 128, 65536>>>(enc);

    // 4. combine -> context, attn weights, prior copy
    combine_kernel<<<dim3(B, 4), 256>>>(prior, out, write_attn);

    // 5. concat GEMM (N=1024, K=2048, ksplit=16) + reduce/tanh
    gemm_kernel<<<dim3(H / 128, 16, 1), 256>>>(
        gcat, gcat, Wc, Wc, pcc, pcc, nullptr, H, H2, 16, H, nullptr);
    creduce_kernel<<<B * H / 256, 256>>>(bc);

    // 6. output GEMM (N=32000, K=1152) via mma.sync fp16 (R8 config)
    out_gemm_tc_kernel<<<V / 128, 256>>>(Wout, bout, out);
}